// round 1
// baseline (speedup 1.0000x reference)
#include <cuda_runtime.h>
#include <cstdint>

// ---------------- problem constants ----------------
#define BB   32
#define SS   512
#define GG   512
#define DD   768
#define GDD  16
#define KX   816           // D + 3*GD
#define M_TOT (BB*SS)      // 16384
#define LN_EPS 1e-12f

// ---------------- device scratch (no allocations allowed) ----------------
__device__ float g_colsum[3][BB][GG];   // (1/G) * column sums of adj
__device__ float g_graph[BB][3*GDD];    // concat(relu(g@W^T+b)) per sample
__device__ float g_gproj[BB][DD];       // graph part of projection + b_proj

// =====================================================================
// Kernel 1: column sums of the three adjacency tensors (coalesced rows)
// grid (B, 3), block 256
// =====================================================================
__global__ __launch_bounds__(256)
void colsum_kernel(const float* __restrict__ a0,
                   const float* __restrict__ a1,
                   const float* __restrict__ a2)
{
    int b = blockIdx.x, gi = blockIdx.y;
    const float* adj = (gi == 0 ? a0 : (gi == 1 ? a1 : a2)) + (size_t)b * GG * GG;
    for (int h = threadIdx.x; h < GG; h += blockDim.x) {
        float acc = 0.f;
        #pragma unroll 4
        for (int g = 0; g < GG; ++g)
            acc += adj[(size_t)g * GG + h];
        g_colsum[gi][b][h] = acc * (1.0f / GG);
    }
}

// =====================================================================
// Kernel 2: g[b,d] = sum_h w[h] * word_emb[gv[b,h], d]; then fc+relu
// grid (B, 3), block 768
// =====================================================================
__global__ __launch_bounds__(768)
void gvec_kernel(const float* __restrict__ word_emb,
                 const int* __restrict__ gv0, const int* __restrict__ gv1, const int* __restrict__ gv2,
                 const float* __restrict__ W0, const float* __restrict__ W1, const float* __restrict__ W2,
                 const float* __restrict__ c0, const float* __restrict__ c1, const float* __restrict__ c2)
{
    int b = blockIdx.x, gi = blockIdx.y;
    const int*   gv   = (gi == 0 ? gv0 : (gi == 1 ? gv1 : gv2));
    const float* W    = (gi == 0 ? W0  : (gi == 1 ? W1  : W2));
    const float* bias = (gi == 0 ? c0  : (gi == 1 ? c1  : c2));

    __shared__ float ws[GG];
    __shared__ int   ids[GG];
    __shared__ float gbuf[DD];

    int t = threadIdx.x;  // 0..767
    if (t < GG) {
        ws[t]  = g_colsum[gi][b][t];
        ids[t] = gv[b * GG + t];
    }
    __syncthreads();

    float acc = 0.f;
    #pragma unroll 4
    for (int h = 0; h < GG; ++h)
        acc += ws[h] * __ldg(&word_emb[(size_t)ids[h] * DD + t]);
    gbuf[t] = acc;
    __syncthreads();

    int w = t >> 5, lane = t & 31;
    if (w < GDD) {
        float s = 0.f;
        #pragma unroll
        for (int d = lane; d < DD; d += 32)
            s += gbuf[d] * W[w * DD + d];
        #pragma unroll
        for (int o = 16; o; o >>= 1)
            s += __shfl_xor_sync(0xffffffffu, s, o);
        if (lane == 0)
            g_graph[b][gi * GDD + w] = fmaxf(s + bias[w], 0.f);
    }
}

// =====================================================================
// Kernel 3: gproj[b,d] = b_proj[d] + sum_j graph[b,j] * W_proj[d, 768+j]
// grid B, block 768
// =====================================================================
__global__ __launch_bounds__(768)
void gproj_kernel(const float* __restrict__ Wp, const float* __restrict__ bp)
{
    int b = blockIdx.x, d = threadIdx.x;
    __shared__ float gr[3 * GDD];
    if (d < 3 * GDD) gr[d] = g_graph[b][d];
    __syncthreads();
    float acc = bp[d];
    #pragma unroll
    for (int j = 0; j < 3 * GDD; ++j)
        acc += gr[j] * Wp[(size_t)d * KX + DD + j];
    g_gproj[b][d] = acc;
}

// =====================================================================
// Kernel 4: main GEMM  C[m,n] = sum_k (word_emb[id[m],k]+pos_emb[s,k]) * Wp[n,k]
//           + gproj[b,n]      (M=16384, N=768, K=768)
// BM=128, BN=128, BK=16, 256 threads, 8x8 thread tile
// =====================================================================
#define BM 128
#define BN 128
#define BK 16

__global__ __launch_bounds__(256)
void gemm_kernel(const int*   __restrict__ input_ids,
                 const float* __restrict__ word_emb,
                 const float* __restrict__ pos_emb,
                 const float* __restrict__ Wp,
                 float*       __restrict__ out)
{
    __shared__ float As[BK][BM];
    __shared__ float Bs[BK][BN];

    const int tid = threadIdx.x;
    const int tx  = tid & 15;        // 0..15 -> n
    const int ty  = tid >> 4;        // 0..15 -> m
    const int m0  = blockIdx.y * BM;
    const int n0  = blockIdx.x * BN;

    // loader mapping: 256 threads, each loads 2 float4 per tile per operand
    const int lrow = tid >> 2;       // 0..63
    const int kq   = (tid & 3) * 4;  // 0,4,8,12

    // A rows this thread loads (gathered): rows lrow and lrow+64
    const int mA0 = m0 + lrow;
    const int mA1 = m0 + lrow + 64;
    const float* __restrict__ wa0 = word_emb + (size_t)__ldg(&input_ids[mA0]) * DD;
    const float* __restrict__ wa1 = word_emb + (size_t)__ldg(&input_ids[mA1]) * DD;
    const float* __restrict__ pa0 = pos_emb + (size_t)(mA0 & (SS - 1)) * DD;
    const float* __restrict__ pa1 = pos_emb + (size_t)(mA1 & (SS - 1)) * DD;

    // B rows (Wp rows = output columns n)
    const float* __restrict__ wb0 = Wp + (size_t)(n0 + lrow) * KX;
    const float* __restrict__ wb1 = Wp + (size_t)(n0 + lrow + 64) * KX;

    float acc[8][8];
    #pragma unroll
    for (int i = 0; i < 8; ++i)
        #pragma unroll
        for (int j = 0; j < 8; ++j) acc[i][j] = 0.f;

    for (int k0 = 0; k0 < DD; k0 += BK) {
        // ---- load A tile (gather + add pos) transposed into As[k][m] ----
        float4 a0 = *(const float4*)(wa0 + k0 + kq);
        float4 p0 = *(const float4*)(pa0 + k0 + kq);
        float4 a1 = *(const float4*)(wa1 + k0 + kq);
        float4 p1 = *(const float4*)(pa1 + k0 + kq);
        As[kq + 0][lrow]      = a0.x + p0.x;
        As[kq + 1][lrow]      = a0.y + p0.y;
        As[kq + 2][lrow]      = a0.z + p0.z;
        As[kq + 3][lrow]      = a0.w + p0.w;
        As[kq + 0][lrow + 64] = a1.x + p1.x;
        As[kq + 1][lrow + 64] = a1.y + p1.y;
        As[kq + 2][lrow + 64] = a1.z + p1.z;
        As[kq + 3][lrow + 64] = a1.w + p1.w;
        // ---- load B tile transposed into Bs[k][n] ----
        float4 b0 = *(const float4*)(wb0 + k0 + kq);
        float4 b1 = *(const float4*)(wb1 + k0 + kq);
        Bs[kq + 0][lrow]      = b0.x;
        Bs[kq + 1][lrow]      = b0.y;
        Bs[kq + 2][lrow]      = b0.z;
        Bs[kq + 3][lrow]      = b0.w;
        Bs[kq + 0][lrow + 64] = b1.x;
        Bs[kq + 1][lrow + 64] = b1.y;
        Bs[kq + 2][lrow + 64] = b1.z;
        Bs[kq + 3][lrow + 64] = b1.w;
        __syncthreads();

        #pragma unroll
        for (int k = 0; k < BK; ++k) {
            float af[8], bf[8];
            #pragma unroll
            for (int i = 0; i < 8; ++i) af[i] = As[k][ty * 8 + i];
            #pragma unroll
            for (int j = 0; j < 8; ++j) bf[j] = Bs[k][tx * 8 + j];
            #pragma unroll
            for (int i = 0; i < 8; ++i)
                #pragma unroll
                for (int j = 0; j < 8; ++j)
                    acc[i][j] = fmaf(af[i], bf[j], acc[i][j]);
        }
        __syncthreads();
    }

    // ---- epilogue: + gproj[b, n], write out ----
    const int bidx = m0 / SS;                 // constant per block (128 | 512)
    const float* __restrict__ gp = &g_gproj[bidx][0];
    #pragma unroll
    for (int i = 0; i < 8; ++i) {
        const int m = m0 + ty * 8 + i;
        float* orow = out + (size_t)m * DD + n0 + tx * 8;
        #pragma unroll
        for (int jq = 0; jq < 8; jq += 4) {
            float4 r;
            r.x = acc[i][jq + 0] + gp[n0 + tx * 8 + jq + 0];
            r.y = acc[i][jq + 1] + gp[n0 + tx * 8 + jq + 1];
            r.z = acc[i][jq + 2] + gp[n0 + tx * 8 + jq + 2];
            r.w = acc[i][jq + 3] + gp[n0 + tx * 8 + jq + 3];
            *(float4*)(orow + jq) = r;
        }
    }
}

// =====================================================================
// Kernel 5: in-place LayerNorm over last dim (768), grid = 16384 rows
// =====================================================================
__global__ __launch_bounds__(256)
void ln_kernel(float* __restrict__ y,
               const float* __restrict__ gamma,
               const float* __restrict__ beta)
{
    const int m = blockIdx.x;
    float* row = y + (size_t)m * DD;
    const int t = threadIdx.x;

    float v[3];
    float s = 0.f, s2 = 0.f;
    #pragma unroll
    for (int i = 0; i < 3; ++i) {
        v[i] = row[t + i * 256];
        s  += v[i];
        s2 += v[i] * v[i];
    }
    #pragma unroll
    for (int o = 16; o; o >>= 1) {
        s  += __shfl_xor_sync(0xffffffffu, s,  o);
        s2 += __shfl_xor_sync(0xffffffffu, s2, o);
    }
    __shared__ float red[2][8];
    const int w = t >> 5, lane = t & 31;
    if (lane == 0) { red[0][w] = s; red[1][w] = s2; }
    __syncthreads();
    s = 0.f; s2 = 0.f;
    #pragma unroll
    for (int i = 0; i < 8; ++i) { s += red[0][i]; s2 += red[1][i]; }

    const float mean = s * (1.0f / DD);
    float var = s2 * (1.0f / DD) - mean * mean;
    var = fmaxf(var, 0.f);
    const float rstd = rsqrtf(var + LN_EPS);

    #pragma unroll
    for (int i = 0; i < 3; ++i) {
        const int d = t + i * 256;
        row[d] = (v[i] - mean) * rstd * gamma[d] + beta[d];
    }
}

// =====================================================================
// launch
// =====================================================================
extern "C" void kernel_launch(void* const* d_in, const int* in_sizes, int n_in,
                              void* d_out, int out_size)
{
    const int*   input_ids = (const int*)  d_in[0];
    const float* adj_cooc  = (const float*)d_in[1];
    const int*   gv_cooc   = (const int*)  d_in[2];
    const float* adj_het   = (const float*)d_in[3];
    const int*   gv_het    = (const int*)  d_in[4];
    const float* adj_isg   = (const float*)d_in[5];
    const int*   gv_isg    = (const int*)  d_in[6];
    const float* word_emb  = (const float*)d_in[7];
    const float* pos_emb   = (const float*)d_in[8];
    const float* W_cooc    = (const float*)d_in[9];
    const float* b_cooc    = (const float*)d_in[10];
    const float* W_het     = (const float*)d_in[11];
    const float* b_het     = (const float*)d_in[12];
    const float* W_isg     = (const float*)d_in[13];
    const float* b_isg     = (const float*)d_in[14];
    const float* W_proj    = (const float*)d_in[15];
    const float* b_proj    = (const float*)d_in[16];
    const float* ln_gamma  = (const float*)d_in[17];
    const float* ln_beta   = (const float*)d_in[18];
    float* out = (float*)d_out;

    colsum_kernel<<<dim3(BB, 3), 256>>>(adj_cooc, adj_het, adj_isg);
    gvec_kernel<<<dim3(BB, 3), 768>>>(word_emb, gv_cooc, gv_het, gv_isg,
                                      W_cooc, W_het, W_isg,
                                      b_cooc, b_het, b_isg);
    gproj_kernel<<<BB, 768>>>(W_proj, b_proj);
    gemm_kernel<<<dim3(DD / BN, M_TOT / BM), 256>>>(input_ids, word_emb, pos_emb,
                                                    W_proj, out);
    ln_kernel<<<M_TOT, 256>>>(out, ln_gamma, ln_beta);
}

// round 2
// speedup vs baseline: 1.5056x; 1.5056x over previous
#include <cuda_runtime.h>
#include <cstdint>

// ---------------- problem constants ----------------
#define BB   32
#define SS   512
#define GG   512
#define DD   768
#define GDD  16
#define KX   816           // D + 3*GD
#define M_TOT (BB*SS)      // 16384
#define LN_EPS 1e-12f

// ---------------- device scratch ----------------
__device__ float g_colpart[3][BB][4][GG];    // partial column sums of adj
__device__ float g_gpart[3][BB][4][DD];      // partial graph vectors
__device__ float g_graph[BB][3*GDD];         // concat(relu(g@W^T+b))
__device__ float g_gproj[BB][DD];            // graph part of projection + b_proj

// =====================================================================
// Kernel 1: partial column sums of adj (4 g-chunks per (b,graph))
// grid (B, 3, 4), block 256
// =====================================================================
__global__ __launch_bounds__(256)
void colsum_kernel(const float* __restrict__ a0,
                   const float* __restrict__ a1,
                   const float* __restrict__ a2)
{
    int b = blockIdx.x, gi = blockIdx.y, c = blockIdx.z;
    const float* adj = (gi == 0 ? a0 : (gi == 1 ? a1 : a2))
                       + (size_t)b * GG * GG + (size_t)c * 128 * GG;
    for (int h = threadIdx.x; h < GG; h += blockDim.x) {
        float acc = 0.f;
        #pragma unroll 8
        for (int g = 0; g < 128; ++g)
            acc += adj[(size_t)g * GG + h];
        g_colpart[gi][b][c][h] = acc;
    }
}

// =====================================================================
// Kernel 2a: partial g[b,d] over a 128-node chunk of h
// grid (B, 3, 4), block 768
// =====================================================================
__global__ __launch_bounds__(768)
void gvec_part_kernel(const float* __restrict__ word_emb,
                      const int* __restrict__ gv0, const int* __restrict__ gv1,
                      const int* __restrict__ gv2)
{
    int b = blockIdx.x, gi = blockIdx.y, c = blockIdx.z;
    const int* gv = (gi == 0 ? gv0 : (gi == 1 ? gv1 : gv2));

    __shared__ float ws[128];
    __shared__ int   ids[128];
    int t = threadIdx.x;
    if (t < 128) {
        int h = c * 128 + t;
        float s = g_colpart[gi][b][0][h] + g_colpart[gi][b][1][h]
                + g_colpart[gi][b][2][h] + g_colpart[gi][b][3][h];
        ws[t]  = s * (1.0f / GG);
        ids[t] = gv[b * GG + h];
    }
    __syncthreads();

    float acc = 0.f;
    #pragma unroll 8
    for (int h = 0; h < 128; ++h)
        acc += ws[h] * __ldg(&word_emb[(size_t)ids[h] * DD + t]);
    g_gpart[gi][b][c][t] = acc;
}

// =====================================================================
// Kernel 2b: reduce partials + fc + relu
// grid (B, 3), block 768
// =====================================================================
__global__ __launch_bounds__(768)
void gvec_fc_kernel(const float* __restrict__ W0, const float* __restrict__ W1,
                    const float* __restrict__ W2,
                    const float* __restrict__ c0, const float* __restrict__ c1,
                    const float* __restrict__ c2)
{
    int b = blockIdx.x, gi = blockIdx.y;
    const float* W    = (gi == 0 ? W0 : (gi == 1 ? W1 : W2));
    const float* bias = (gi == 0 ? c0 : (gi == 1 ? c1 : c2));

    __shared__ float gbuf[DD];
    int t = threadIdx.x;
    gbuf[t] = g_gpart[gi][b][0][t] + g_gpart[gi][b][1][t]
            + g_gpart[gi][b][2][t] + g_gpart[gi][b][3][t];
    __syncthreads();

    int w = t >> 5, lane = t & 31;
    if (w < GDD) {
        float s = 0.f;
        #pragma unroll
        for (int d = lane; d < DD; d += 32)
            s += gbuf[d] * W[w * DD + d];
        #pragma unroll
        for (int o = 16; o; o >>= 1)
            s += __shfl_xor_sync(0xffffffffu, s, o);
        if (lane == 0)
            g_graph[b][gi * GDD + w] = fmaxf(s + bias[w], 0.f);
    }
}

// =====================================================================
// Kernel 3: gproj[b,d] = b_proj[d] + sum_j graph[b,j] * W_proj[d, 768+j]
// =====================================================================
__global__ __launch_bounds__(768)
void gproj_kernel(const float* __restrict__ Wp, const float* __restrict__ bp)
{
    int b = blockIdx.x, d = threadIdx.x;
    __shared__ float gr[3 * GDD];
    if (d < 3 * GDD) gr[d] = g_graph[b][d];
    __syncthreads();
    float acc = bp[d];
    #pragma unroll
    for (int j = 0; j < 3 * GDD; ++j)
        acc += gr[j] * Wp[(size_t)d * KX + DD + j];
    g_gproj[b][d] = acc;
}

// =====================================================================
// Kernel 4: main GEMM via 3xTF32 mma.sync
//   C[m,n] = sum_k (word_emb[id[m],k]+pos_emb[s,k]) * Wp[n,k] + gproj[b,n]
//   M=16384, N=768, K=768;  BM=BN=128, BK=16, 8 warps (64x32 warp tiles)
// =====================================================================
#define BM 128
#define BN 128
#define BK 16
#define NT_TILES (DD / BK)   // 48
#define PAD 8

__device__ __forceinline__ void split_tf32(float x, uint32_t& hi, uint32_t& lo)
{
    uint32_t h;
    asm("cvt.rna.tf32.f32 %0, %1;" : "=r"(h) : "f"(x));
    float r = x - __uint_as_float(h);
    uint32_t l;
    asm("cvt.rna.tf32.f32 %0, %1;" : "=r"(l) : "f"(r));
    hi = h; lo = l;
}

__device__ __forceinline__ void mma_tf32(float* c, const uint32_t* a, const uint32_t* b)
{
    asm("mma.sync.aligned.m16n8k8.row.col.f32.tf32.tf32.f32 "
        "{%0,%1,%2,%3}, {%4,%5,%6,%7}, {%8,%9}, {%0,%1,%2,%3};"
        : "+f"(c[0]), "+f"(c[1]), "+f"(c[2]), "+f"(c[3])
        : "r"(a[0]), "r"(a[1]), "r"(a[2]), "r"(a[3]), "r"(b[0]), "r"(b[1]));
}

__global__ __launch_bounds__(256, 1)
void gemm_kernel(const int*   __restrict__ input_ids,
                 const float* __restrict__ word_emb,
                 const float* __restrict__ pos_emb,
                 const float* __restrict__ Wp,
                 float*       __restrict__ out)
{
    __shared__ float As[2][BK][BM + PAD];
    __shared__ float Bs[2][BK][BN + PAD];

    const int tid = threadIdx.x;
    const int m0  = blockIdx.y * BM;
    const int n0  = blockIdx.x * BN;

    // warp tiling: 2 (M) x 4 (N) warps, warp tile 64x32
    const int warpId = tid >> 5;
    const int lane   = tid & 31;
    const int mW     = (warpId & 1) * 64;
    const int nW     = (warpId >> 1) * 32;
    const int g      = lane >> 2;     // groupID 0..7
    const int tg     = lane & 3;      // thread-in-group 0..3

    // loader mapping: each thread loads 2 float4 per operand per tile
    const int lrow = tid >> 2;        // 0..63
    const int kq   = (tid & 3) * 4;   // 0,4,8,12

    const int mA0 = m0 + lrow;
    const int mA1 = m0 + lrow + 64;
    const float* __restrict__ wa0 = word_emb + (size_t)__ldg(&input_ids[mA0]) * DD;
    const float* __restrict__ wa1 = word_emb + (size_t)__ldg(&input_ids[mA1]) * DD;
    const float* __restrict__ pa0 = pos_emb + (size_t)(mA0 & (SS - 1)) * DD;
    const float* __restrict__ pa1 = pos_emb + (size_t)(mA1 & (SS - 1)) * DD;
    const float* __restrict__ wb0 = Wp + (size_t)(n0 + lrow) * KX;
    const float* __restrict__ wb1 = Wp + (size_t)(n0 + lrow + 64) * KX;

    float acc[4][4][4];
    #pragma unroll
    for (int mt = 0; mt < 4; ++mt)
        #pragma unroll
        for (int nt = 0; nt < 4; ++nt)
            #pragma unroll
            for (int r = 0; r < 4; ++r) acc[mt][nt][r] = 0.f;

    // ---- preload tile 0 into buffer 0 ----
    {
        float4 a0 = *(const float4*)(wa0 + kq);
        float4 p0 = *(const float4*)(pa0 + kq);
        float4 a1 = *(const float4*)(wa1 + kq);
        float4 p1 = *(const float4*)(pa1 + kq);
        float4 b0 = *(const float4*)(wb0 + kq);
        float4 b1 = *(const float4*)(wb1 + kq);
        As[0][kq + 0][lrow]      = a0.x + p0.x;
        As[0][kq + 1][lrow]      = a0.y + p0.y;
        As[0][kq + 2][lrow]      = a0.z + p0.z;
        As[0][kq + 3][lrow]      = a0.w + p0.w;
        As[0][kq + 0][lrow + 64] = a1.x + p1.x;
        As[0][kq + 1][lrow + 64] = a1.y + p1.y;
        As[0][kq + 2][lrow + 64] = a1.z + p1.z;
        As[0][kq + 3][lrow + 64] = a1.w + p1.w;
        Bs[0][kq + 0][lrow]      = b0.x;
        Bs[0][kq + 1][lrow]      = b0.y;
        Bs[0][kq + 2][lrow]      = b0.z;
        Bs[0][kq + 3][lrow]      = b0.w;
        Bs[0][kq + 0][lrow + 64] = b1.x;
        Bs[0][kq + 1][lrow + 64] = b1.y;
        Bs[0][kq + 2][lrow + 64] = b1.z;
        Bs[0][kq + 3][lrow + 64] = b1.w;
    }
    __syncthreads();

    int buf = 0;
    for (int t = 0; t < NT_TILES; ++t) {
        const bool has_next = (t + 1 < NT_TILES);
        float4 ra0, rp0, ra1, rp1, rb0, rb1;
        if (has_next) {
            const int k0 = (t + 1) * BK + kq;
            ra0 = *(const float4*)(wa0 + k0);
            rp0 = *(const float4*)(pa0 + k0);
            ra1 = *(const float4*)(wa1 + k0);
            rp1 = *(const float4*)(pa1 + k0);
            rb0 = *(const float4*)(wb0 + k0);
            rb1 = *(const float4*)(wb1 + k0);
        }

        // ---- compute current tile: 2 k-steps of 8 ----
        #pragma unroll
        for (int kk = 0; kk < BK; kk += 8) {
            uint32_t bhi[4][2], blo[4][2];
            #pragma unroll
            for (int nt = 0; nt < 4; ++nt) {
                float b0 = Bs[buf][kk + tg][nW + nt * 8 + g];
                float b1 = Bs[buf][kk + tg + 4][nW + nt * 8 + g];
                split_tf32(b0, bhi[nt][0], blo[nt][0]);
                split_tf32(b1, bhi[nt][1], blo[nt][1]);
            }
            #pragma unroll
            for (int mt = 0; mt < 4; ++mt) {
                float a0 = As[buf][kk + tg][mW + mt * 16 + g];
                float a1 = As[buf][kk + tg][mW + mt * 16 + g + 8];
                float a2 = As[buf][kk + tg + 4][mW + mt * 16 + g];
                float a3 = As[buf][kk + tg + 4][mW + mt * 16 + g + 8];
                uint32_t ahi[4], alo[4];
                split_tf32(a0, ahi[0], alo[0]);
                split_tf32(a1, ahi[1], alo[1]);
                split_tf32(a2, ahi[2], alo[2]);
                split_tf32(a3, ahi[3], alo[3]);
                #pragma unroll
                for (int nt = 0; nt < 4; ++nt) {
                    mma_tf32(acc[mt][nt], ahi, bhi[nt]);
                    mma_tf32(acc[mt][nt], alo, bhi[nt]);
                    mma_tf32(acc[mt][nt], ahi, blo[nt]);
                }
            }
        }

        if (has_next) {
            const int nb = buf ^ 1;
            As[nb][kq + 0][lrow]      = ra0.x + rp0.x;
            As[nb][kq + 1][lrow]      = ra0.y + rp0.y;
            As[nb][kq + 2][lrow]      = ra0.z + rp0.z;
            As[nb][kq + 3][lrow]      = ra0.w + rp0.w;
            As[nb][kq + 0][lrow + 64] = ra1.x + rp1.x;
            As[nb][kq + 1][lrow + 64] = ra1.y + rp1.y;
            As[nb][kq + 2][lrow + 64] = ra1.z + rp1.z;
            As[nb][kq + 3][lrow + 64] = ra1.w + rp1.w;
            Bs[nb][kq + 0][lrow]      = rb0.x;
            Bs[nb][kq + 1][lrow]      = rb0.y;
            Bs[nb][kq + 2][lrow]      = rb0.z;
            Bs[nb][kq + 3][lrow]      = rb0.w;
            Bs[nb][kq + 0][lrow + 64] = rb1.x;
            Bs[nb][kq + 1][lrow + 64] = rb1.y;
            Bs[nb][kq + 2][lrow + 64] = rb1.z;
            Bs[nb][kq + 3][lrow + 64] = rb1.w;
        }
        __syncthreads();
        buf ^= 1;
    }

    // ---- epilogue: + gproj[b, n], write out ----
    const int bidx = m0 / SS;
    const float* __restrict__ gp = &g_gproj[bidx][0];
    #pragma unroll
    for (int mt = 0; mt < 4; ++mt) {
        const int mBase = m0 + mW + mt * 16 + g;
        #pragma unroll
        for (int nt = 0; nt < 4; ++nt) {
            const int n = n0 + nW + nt * 8 + tg * 2;
            float2 r0, r1;
            r0.x = acc[mt][nt][0] + gp[n];
            r0.y = acc[mt][nt][1] + gp[n + 1];
            r1.x = acc[mt][nt][2] + gp[n];
            r1.y = acc[mt][nt][3] + gp[n + 1];
            *(float2*)(out + (size_t)mBase * DD + n)       = r0;
            *(float2*)(out + (size_t)(mBase + 8) * DD + n) = r1;
        }
    }
}

// =====================================================================
// Kernel 5: in-place LayerNorm over last dim (768), grid = 16384 rows
// =====================================================================
__global__ __launch_bounds__(256)
void ln_kernel(float* __restrict__ y,
               const float* __restrict__ gamma,
               const float* __restrict__ beta)
{
    const int m = blockIdx.x;
    float* row = y + (size_t)m * DD;
    const int t = threadIdx.x;

    float v[3];
    float s = 0.f, s2 = 0.f;
    #pragma unroll
    for (int i = 0; i < 3; ++i) {
        v[i] = row[t + i * 256];
        s  += v[i];
        s2 += v[i] * v[i];
    }
    #pragma unroll
    for (int o = 16; o; o >>= 1) {
        s  += __shfl_xor_sync(0xffffffffu, s,  o);
        s2 += __shfl_xor_sync(0xffffffffu, s2, o);
    }
    __shared__ float red[2][8];
    const int w = t >> 5, lane = t & 31;
    if (lane == 0) { red[0][w] = s; red[1][w] = s2; }
    __syncthreads();
    s = 0.f; s2 = 0.f;
    #pragma unroll
    for (int i = 0; i < 8; ++i) { s += red[0][i]; s2 += red[1][i]; }

    const float mean = s * (1.0f / DD);
    float var = s2 * (1.0f / DD) - mean * mean;
    var = fmaxf(var, 0.f);
    const float rstd = rsqrtf(var + LN_EPS);

    #pragma unroll
    for (int i = 0; i < 3; ++i) {
        const int d = t + i * 256;
        row[d] = (v[i] - mean) * rstd * gamma[d] + beta[d];
    }
}

// =====================================================================
// launch
// =====================================================================
extern "C" void kernel_launch(void* const* d_in, const int* in_sizes, int n_in,
                              void* d_out, int out_size)
{
    const int*   input_ids = (const int*)  d_in[0];
    const float* adj_cooc  = (const float*)d_in[1];
    const int*   gv_cooc   = (const int*)  d_in[2];
    const float* adj_het   = (const float*)d_in[3];
    const int*   gv_het    = (const int*)  d_in[4];
    const float* adj_isg   = (const float*)d_in[5];
    const int*   gv_isg    = (const int*)  d_in[6];
    const float* word_emb  = (const float*)d_in[7];
    const float* pos_emb   = (const float*)d_in[8];
    const float* W_cooc    = (const float*)d_in[9];
    const float* b_cooc    = (const float*)d_in[10];
    const float* W_het     = (const float*)d_in[11];
    const float* b_het     = (const float*)d_in[12];
    const float* W_isg     = (const float*)d_in[13];
    const float* b_isg     = (const float*)d_in[14];
    const float* W_proj    = (const float*)d_in[15];
    const float* b_proj    = (const float*)d_in[16];
    const float* ln_gamma  = (const float*)d_in[17];
    const float* ln_beta   = (const float*)d_in[18];
    float* out = (float*)d_out;

    colsum_kernel<<<dim3(BB, 3, 4), 256>>>(adj_cooc, adj_het, adj_isg);
    gvec_part_kernel<<<dim3(BB, 3, 4), 768>>>(word_emb, gv_cooc, gv_het, gv_isg);
    gvec_fc_kernel<<<dim3(BB, 3), 768>>>(W_cooc, W_het, W_isg,
                                         b_cooc, b_het, b_isg);
    gproj_kernel<<<BB, 768>>>(W_proj, b_proj);
    gemm_kernel<<<dim3(DD / BN, M_TOT / BM), 256>>>(input_ids, word_emb, pos_emb,
                                                    W_proj, out);
    ln_kernel<<<M_TOT, 256>>>(out, ln_gamma, ln_beta);
}

// round 8
// speedup vs baseline: 2.4659x; 1.6379x over previous
#include <cuda_runtime.h>
#include <cstdint>

// ---------------- problem constants ----------------
#define BB   32
#define SS   512
#define GG   512
#define DD   768
#define GDD  16
#define KX   816           // D + 3*GD
#define M_TOT (BB*SS)      // 16384
#define LN_EPS 1e-12f

// ---------------- device scratch ----------------
__device__ float g_colpart[3][BB][4][GG];    // partial column sums of adj
__device__ float g_gpart[3][BB][4][DD];      // partial graph vectors
__device__ float g_graph[BB][3*GDD];         // concat(relu(g@W^T+b))

// =====================================================================
// Kernel 1: partial column sums of adj; grid (B, 3, 4), block 256
// =====================================================================
__global__ __launch_bounds__(256)
void colsum_kernel(const float* __restrict__ a0,
                   const float* __restrict__ a1,
                   const float* __restrict__ a2)
{
    int b = blockIdx.x, gi = blockIdx.y, c = blockIdx.z;
    const float* adj = (gi == 0 ? a0 : (gi == 1 ? a1 : a2))
                       + (size_t)b * GG * GG + (size_t)c * 128 * GG;
    for (int h = threadIdx.x; h < GG; h += blockDim.x) {
        float acc = 0.f;
        #pragma unroll 8
        for (int g = 0; g < 128; ++g)
            acc += adj[(size_t)g * GG + h];
        g_colpart[gi][b][c][h] = acc;
    }
}

// =====================================================================
// Kernel 2a: partial g[b,d] over a 128-node chunk; grid (B,3,4), block 768
// =====================================================================
__global__ __launch_bounds__(768)
void gvec_part_kernel(const float* __restrict__ word_emb,
                      const int* __restrict__ gv0, const int* __restrict__ gv1,
                      const int* __restrict__ gv2)
{
    int b = blockIdx.x, gi = blockIdx.y, c = blockIdx.z;
    const int* gv = (gi == 0 ? gv0 : (gi == 1 ? gv1 : gv2));

    __shared__ float ws[128];
    __shared__ int   ids[128];
    int t = threadIdx.x;
    if (t < 128) {
        int h = c * 128 + t;
        float s = g_colpart[gi][b][0][h] + g_colpart[gi][b][1][h]
                + g_colpart[gi][b][2][h] + g_colpart[gi][b][3][h];
        ws[t]  = s * (1.0f / GG);
        ids[t] = gv[b * GG + h];
    }
    __syncthreads();

    float acc = 0.f;
    #pragma unroll 8
    for (int h = 0; h < 128; ++h)
        acc += ws[h] * __ldg(&word_emb[(size_t)ids[h] * DD + t]);
    g_gpart[gi][b][c][t] = acc;
}

// =====================================================================
// Kernel 2b: reduce partials + fc + relu; grid (B,3), block 768
// =====================================================================
__global__ __launch_bounds__(768)
void gvec_fc_kernel(const float* __restrict__ W0, const float* __restrict__ W1,
                    const float* __restrict__ W2,
                    const float* __restrict__ c0, const float* __restrict__ c1,
                    const float* __restrict__ c2)
{
    int b = blockIdx.x, gi = blockIdx.y;
    const float* W    = (gi == 0 ? W0 : (gi == 1 ? W1 : W2));
    const float* bias = (gi == 0 ? c0 : (gi == 1 ? c1 : c2));

    __shared__ float gbuf[DD];
    int t = threadIdx.x;
    gbuf[t] = g_gpart[gi][b][0][t] + g_gpart[gi][b][1][t]
            + g_gpart[gi][b][2][t] + g_gpart[gi][b][3][t];
    __syncthreads();

    int w = t >> 5, lane = t & 31;
    if (w < GDD) {
        float s = 0.f;
        #pragma unroll
        for (int d = lane; d < DD; d += 32)
            s += gbuf[d] * W[w * DD + d];
        #pragma unroll
        for (int o = 16; o; o >>= 1)
            s += __shfl_xor_sync(0xffffffffu, s, o);
        if (lane == 0)
            g_graph[b][gi * GDD + w] = fmaxf(s + bias[w], 0.f);
    }
}

// =====================================================================
// Kernel 3: main GEMM via single-pass TF32 mma.sync (rna-rounded operands)
//   C[m,n] = sum_k tf32(word_emb[id[m],k]+pos_emb[s,k]) * tf32(Wp[n,k])
//            + gproj[b,n]   (gproj fused: graph half of projection + bias)
//   M=16384, N=768, K=768;  BM=BN=128, BK=16, 8 warps (64x32 warp tiles)
// =====================================================================
#define BM 128
#define BN 128
#define BK 16
#define NT_TILES (DD / BK)   // 48
#define PAD 8

__device__ __forceinline__ uint32_t to_tf32(float x)
{
    uint32_t h;
    asm("cvt.rna.tf32.f32 %0, %1;" : "=r"(h) : "f"(x));
    return h;
}

__device__ __forceinline__ void mma_tf32(float* c, const uint32_t* a, const uint32_t* b)
{
    asm("mma.sync.aligned.m16n8k8.row.col.f32.tf32.tf32.f32 "
        "{%0,%1,%2,%3}, {%4,%5,%6,%7}, {%8,%9}, {%0,%1,%2,%3};"
        : "+f"(c[0]), "+f"(c[1]), "+f"(c[2]), "+f"(c[3])
        : "r"(a[0]), "r"(a[1]), "r"(a[2]), "r"(a[3]), "r"(b[0]), "r"(b[1]));
}

__global__ __launch_bounds__(256, 2)
void gemm_kernel(const int*   __restrict__ input_ids,
                 const float* __restrict__ word_emb,
                 const float* __restrict__ pos_emb,
                 const float* __restrict__ Wp,
                 const float* __restrict__ b_proj,
                 float*       __restrict__ out)
{
    __shared__ uint32_t As[2][BK][BM + PAD];
    __shared__ uint32_t Bs[2][BK][BN + PAD];
    __shared__ float grs[3 * GDD];
    __shared__ float gpn[BN];

    const int tid = threadIdx.x;
    const int m0  = blockIdx.y * BM;
    const int n0  = blockIdx.x * BN;
    const int bidx = blockIdx.y >> 2;     // m0 / SS

    // warp tiling: 2 (M) x 4 (N) warps, warp tile 64x32
    const int warpId = tid >> 5;
    const int lane   = tid & 31;
    const int mW     = (warpId & 1) * 64;
    const int nW     = (warpId >> 1) * 32;
    const int g      = lane >> 2;     // groupID 0..7
    const int tg     = lane & 3;      // thread-in-group 0..3

    // loader mapping: each thread loads 2 float4 per operand per tile
    const int lrow = tid >> 2;        // 0..63
    const int kq   = (tid & 3) * 4;   // 0,4,8,12

    const int mA0 = m0 + lrow;
    const int mA1 = m0 + lrow + 64;
    const float* __restrict__ wa0 = word_emb + (size_t)__ldg(&input_ids[mA0]) * DD;
    const float* __restrict__ wa1 = word_emb + (size_t)__ldg(&input_ids[mA1]) * DD;
    const float* __restrict__ pa0 = pos_emb + (size_t)(mA0 & (SS - 1)) * DD;
    const float* __restrict__ pa1 = pos_emb + (size_t)(mA1 & (SS - 1)) * DD;
    const float* __restrict__ wb0 = Wp + (size_t)(n0 + lrow) * KX;
    const float* __restrict__ wb1 = Wp + (size_t)(n0 + lrow + 64) * KX;

    float acc[4][4][4];
    #pragma unroll
    for (int mt = 0; mt < 4; ++mt)
        #pragma unroll
        for (int nt = 0; nt < 4; ++nt)
            #pragma unroll
            for (int r = 0; r < 4; ++r) acc[mt][nt][r] = 0.f;

    // ---- stage graph vector for fused gproj ----
    if (tid < 3 * GDD) grs[tid] = g_graph[bidx][tid];

    // ---- preload tile 0 into buffer 0 ----
    {
        float4 a0 = *(const float4*)(wa0 + kq);
        float4 p0 = *(const float4*)(pa0 + kq);
        float4 a1 = *(const float4*)(wa1 + kq);
        float4 p1 = *(const float4*)(pa1 + kq);
        float4 b0 = *(const float4*)(wb0 + kq);
        float4 b1 = *(const float4*)(wb1 + kq);
        As[0][kq + 0][lrow]      = to_tf32(a0.x + p0.x);
        As[0][kq + 1][lrow]      = to_tf32(a0.y + p0.y);
        As[0][kq + 2][lrow]      = to_tf32(a0.z + p0.z);
        As[0][kq + 3][lrow]      = to_tf32(a0.w + p0.w);
        As[0][kq + 0][lrow + 64] = to_tf32(a1.x + p1.x);
        As[0][kq + 1][lrow + 64] = to_tf32(a1.y + p1.y);
        As[0][kq + 2][lrow + 64] = to_tf32(a1.z + p1.z);
        As[0][kq + 3][lrow + 64] = to_tf32(a1.w + p1.w);
        Bs[0][kq + 0][lrow]      = to_tf32(b0.x);
        Bs[0][kq + 1][lrow]      = to_tf32(b0.y);
        Bs[0][kq + 2][lrow]      = to_tf32(b0.z);
        Bs[0][kq + 3][lrow]      = to_tf32(b0.w);
        Bs[0][kq + 0][lrow + 64] = to_tf32(b1.x);
        Bs[0][kq + 1][lrow + 64] = to_tf32(b1.y);
        Bs[0][kq + 2][lrow + 64] = to_tf32(b1.z);
        Bs[0][kq + 3][lrow + 64] = to_tf32(b1.w);
    }
    __syncthreads();

    // ---- fused gproj: gpn[n-n0] = b_proj[n] + sum_j grs[j]*Wp[n,768+j] ----
    if (tid < BN) {
        const float* __restrict__ wrow = Wp + (size_t)(n0 + tid) * KX + DD;
        float a = b_proj[n0 + tid];
        #pragma unroll
        for (int j = 0; j < 3 * GDD; ++j)
            a += grs[j] * wrow[j];
        gpn[tid] = a;   // visible to all after the next __syncthreads in the loop
    }

    int buf = 0;
    for (int t = 0; t < NT_TILES; ++t) {
        const bool has_next = (t + 1 < NT_TILES);
        float4 ra0, rp0, ra1, rp1, rb0, rb1;
        if (has_next) {
            const int k0 = (t + 1) * BK + kq;
            ra0 = *(const float4*)(wa0 + k0);
            rp0 = *(const float4*)(pa0 + k0);
            ra1 = *(const float4*)(wa1 + k0);
            rp1 = *(const float4*)(pa1 + k0);
            rb0 = *(const float4*)(wb0 + k0);
            rb1 = *(const float4*)(wb1 + k0);
        }

        // ---- compute current tile: 2 k-steps of 8 ----
        #pragma unroll
        for (int kk = 0; kk < BK; kk += 8) {
            uint32_t bfr[4][2];
            #pragma unroll
            for (int nt = 0; nt < 4; ++nt) {
                bfr[nt][0] = Bs[buf][kk + tg][nW + nt * 8 + g];
                bfr[nt][1] = Bs[buf][kk + tg + 4][nW + nt * 8 + g];
            }
            #pragma unroll
            for (int mt = 0; mt < 4; ++mt) {
                uint32_t afr[4];
                afr[0] = As[buf][kk + tg][mW + mt * 16 + g];
                afr[1] = As[buf][kk + tg][mW + mt * 16 + g + 8];
                afr[2] = As[buf][kk + tg + 4][mW + mt * 16 + g];
                afr[3] = As[buf][kk + tg + 4][mW + mt * 16 + g + 8];
                #pragma unroll
                for (int nt = 0; nt < 4; ++nt)
                    mma_tf32(acc[mt][nt], afr, bfr[nt]);
            }
        }

        if (has_next) {
            const int nb = buf ^ 1;
            As[nb][kq + 0][lrow]      = to_tf32(ra0.x + rp0.x);
            As[nb][kq + 1][lrow]      = to_tf32(ra0.y + rp0.y);
            As[nb][kq + 2][lrow]      = to_tf32(ra0.z + rp0.z);
            As[nb][kq + 3][lrow]      = to_tf32(ra0.w + rp0.w);
            As[nb][kq + 0][lrow + 64] = to_tf32(ra1.x + rp1.x);
            As[nb][kq + 1][lrow + 64] = to_tf32(ra1.y + rp1.y);
            As[nb][kq + 2][lrow + 64] = to_tf32(ra1.z + rp1.z);
            As[nb][kq + 3][lrow + 64] = to_tf32(ra1.w + rp1.w);
            Bs[nb][kq + 0][lrow]      = to_tf32(rb0.x);
            Bs[nb][kq + 1][lrow]      = to_tf32(rb0.y);
            Bs[nb][kq + 2][lrow]      = to_tf32(rb0.z);
            Bs[nb][kq + 3][lrow]      = to_tf32(rb0.w);
            Bs[nb][kq + 0][lrow + 64] = to_tf32(rb1.x);
            Bs[nb][kq + 1][lrow + 64] = to_tf32(rb1.y);
            Bs[nb][kq + 2][lrow + 64] = to_tf32(rb1.z);
            Bs[nb][kq + 3][lrow + 64] = to_tf32(rb1.w);
        }
        __syncthreads();
        buf ^= 1;
    }

    // ---- epilogue: + gpn[n-n0], write out ----
    #pragma unroll
    for (int mt = 0; mt < 4; ++mt) {
        const int mBase = m0 + mW + mt * 16 + g;
        #pragma unroll
        for (int nt = 0; nt < 4; ++nt) {
            const int nl = nW + nt * 8 + tg * 2;
            float2 r0, r1;
            r0.x = acc[mt][nt][0] + gpn[nl];
            r0.y = acc[mt][nt][1] + gpn[nl + 1];
            r1.x = acc[mt][nt][2] + gpn[nl];
            r1.y = acc[mt][nt][3] + gpn[nl + 1];
            *(float2*)(out + (size_t)mBase * DD + n0 + nl)       = r0;
            *(float2*)(out + (size_t)(mBase + 8) * DD + n0 + nl) = r1;
        }
    }
}

// =====================================================================
// Kernel 4: in-place LayerNorm over last dim (768), grid = 16384 rows
// =====================================================================
__global__ __launch_bounds__(256)
void ln_kernel(float* __restrict__ y,
               const float* __restrict__ gamma,
               const float* __restrict__ beta)
{
    const int m = blockIdx.x;
    float* row = y + (size_t)m * DD;
    const int t = threadIdx.x;

    float v[3];
    float s = 0.f, s2 = 0.f;
    #pragma unroll
    for (int i = 0; i < 3; ++i) {
        v[i] = row[t + i * 256];
        s  += v[i];
        s2 += v[i] * v[i];
    }
    #pragma unroll
    for (int o = 16; o; o >>= 1) {
        s  += __shfl_xor_sync(0xffffffffu, s,  o);
        s2 += __shfl_xor_sync(0xffffffffu, s2, o);
    }
    __shared__ float red[2][8];
    const int w = t >> 5, lane = t & 31;
    if (lane == 0) { red[0][w] = s; red[1][w] = s2; }
    __syncthreads();
    s = 0.f; s2 = 0.f;
    #pragma unroll
    for (int i = 0; i < 8; ++i) { s += red[0][i]; s2 += red[1][i]; }

    const float mean = s * (1.0f / DD);
    float var = s2 * (1.0f / DD) - mean * mean;
    var = fmaxf(var, 0.f);
    const float rstd = rsqrtf(var + LN_EPS);

    #pragma unroll
    for (int i = 0; i < 3; ++i) {
        const int d = t + i * 256;
        row[d] = (v[i] - mean) * rstd * gamma[d] + beta[d];
    }
}

// =====================================================================
// launch
// =====================================================================
extern "C" void kernel_launch(void* const* d_in, const int* in_sizes, int n_in,
                              void* d_out, int out_size)
{
    const int*   input_ids = (const int*)  d_in[0];
    const float* adj_cooc  = (const float*)d_in[1];
    const int*   gv_cooc   = (const int*)  d_in[2];
    const float* adj_het   = (const float*)d_in[3];
    const int*   gv_het    = (const int*)  d_in[4];
    const float* adj_isg   = (const float*)d_in[5];
    const int*   gv_isg    = (const int*)  d_in[6];
    const float* word_emb  = (const float*)d_in[7];
    const float* pos_emb   = (const float*)d_in[8];
    const float* W_cooc    = (const float*)d_in[9];
    const float* b_cooc    = (const float*)d_in[10];
    const float* W_het     = (const float*)d_in[11];
    const float* b_het     = (const float*)d_in[12];
    const float* W_isg     = (const float*)d_in[13];
    const float* b_isg     = (const float*)d_in[14];
    const float* W_proj    = (const float*)d_in[15];
    const float* b_proj    = (const float*)d_in[16];
    const float* ln_gamma  = (const float*)d_in[17];
    const float* ln_beta   = (const float*)d_in[18];
    float* out = (float*)d_out;

    colsum_kernel<<<dim3(BB, 3, 4), 256>>>(adj_cooc, adj_het, adj_isg);
    gvec_part_kernel<<<dim3(BB, 3, 4), 768>>>(word_emb, gv_cooc, gv_het, gv_isg);
    gvec_fc_kernel<<<dim3(BB, 3), 768>>>(W_cooc, W_het, W_isg,
                                         b_cooc, b_het, b_isg);
    gemm_kernel<<<dim3(DD / BN, M_TOT / BM), 256>>>(input_ids, word_emb, pos_emb,
                                                    W_proj, b_proj, out);
    ln_kernel<<<M_TOT, 256>>>(out, ln_gamma, ln_beta);
}